// round 1
// baseline (speedup 1.0000x reference)
#include <cuda_runtime.h>
#include <cuda_bf16.h>
#include <cstdint>

#define I_DIM 1024
#define J_DIM 50000
#define J_PAD 50048      // 391 * 128
#define D_DIM 512
#define NCLS  10

#define BI 128
#define BJ 128
#define BK 32
#define SSTRIDE 20       // u32 per smem row (40 bf16 = 32 + 8 pad) -> conflict-free frag loads

// ---------------- device scratch (static globals: no runtime allocation) ----------------
__device__ __nv_bfloat16 g_xb[I_DIM * D_DIM];      // x * Sigma_inv, bf16
__device__ __nv_bfloat16 g_eb[J_PAD * D_DIM];      // exemplars, bf16 (padded rows zeroed)
__device__ float g_xsq[I_DIM];                     // sum_d S[d]*x^2
__device__ float g_esq[J_PAD];                     // sum_d S[d]*e^2
__device__ float g_logits[I_DIM * NCLS];

// ---------------- prep: convert + row norms ----------------
__global__ void prep_x(const float* __restrict__ x, const float* __restrict__ S) {
    int warp = (blockIdx.x * blockDim.x + threadIdx.x) >> 5;
    int lane = threadIdx.x & 31;
    if (warp >= I_DIM) return;
    const float* xr = x + (size_t)warp * D_DIM;
    float sq = 0.f;
#pragma unroll
    for (int i = 0; i < D_DIM / 32; i++) {
        int k = i * 32 + lane;
        float s = S[k];
        float v = xr[k];
        sq += v * v * s;
        g_xb[(size_t)warp * D_DIM + k] = __float2bfloat16(v * s);
    }
#pragma unroll
    for (int o = 16; o; o >>= 1) sq += __shfl_xor_sync(0xffffffffu, sq, o);
    if (lane == 0) g_xsq[warp] = sq;
}

__global__ void prep_e(const float* __restrict__ e, const float* __restrict__ S) {
    int warp = (blockIdx.x * blockDim.x + threadIdx.x) >> 5;
    int lane = threadIdx.x & 31;
    if (warp >= J_PAD) return;
    if (warp >= J_DIM) {
        // zero-fill pad rows so GEMM tile loads are clean
#pragma unroll
        for (int i = 0; i < D_DIM / 32; i++)
            g_eb[(size_t)warp * D_DIM + i * 32 + lane] = __float2bfloat16(0.f);
        if (lane == 0) g_esq[warp] = 0.f;
        return;
    }
    const float* er = e + (size_t)warp * D_DIM;
    float sq = 0.f;
#pragma unroll
    for (int i = 0; i < D_DIM / 32; i++) {
        int k = i * 32 + lane;
        float s = S[k];
        float v = er[k];
        sq += v * v * s;
        g_eb[(size_t)warp * D_DIM + k] = __float2bfloat16(v);
    }
#pragma unroll
    for (int o = 16; o; o >>= 1) sq += __shfl_xor_sync(0xffffffffu, sq, o);
    if (lane == 0) g_esq[warp] = sq;
}

__global__ void zero_logits() {
    int t = blockIdx.x * blockDim.x + threadIdx.x;
    if (t < I_DIM * NCLS) g_logits[t] = 0.f;
}

// ---------------- fused GEMM (bf16 HMMA) + exp + segment-sum ----------------
__device__ __forceinline__ void mma_bf16(float c[4], const uint32_t a[4], const uint32_t b[2]) {
    asm volatile(
        "mma.sync.aligned.m16n8k16.row.col.f32.bf16.bf16.f32 "
        "{%0,%1,%2,%3}, {%4,%5,%6,%7}, {%8,%9}, {%0,%1,%2,%3};\n"
        : "+f"(c[0]), "+f"(c[1]), "+f"(c[2]), "+f"(c[3])
        : "r"(a[0]), "r"(a[1]), "r"(a[2]), "r"(a[3]), "r"(b[0]), "r"(b[1]));
}

__global__ __launch_bounds__(256, 2)
void gemm_fused(const int* __restrict__ labels, const float* __restrict__ beta_p) {
    __shared__ uint32_t As[BI * SSTRIDE];
    __shared__ uint32_t Bs[BJ * SSTRIDE];
    __shared__ int labs[BJ];

    const int tid  = threadIdx.x;
    const int warp = tid >> 5;
    const int lane = tid & 31;
    const int gid  = lane >> 2;   // 0..7
    const int tig  = lane & 3;    // 0..3
    const int iBase = blockIdx.x * BI;
    const int jBase = blockIdx.y * BJ;
    const int wi = warp & 1;      // i-half: 0..1 (64 rows)
    const int wj = warp >> 1;     // j-quarter: 0..3 (32 cols)

    const float beta = beta_p[0];

    if (tid < BJ) {
        int j = jBase + tid;
        labs[tid] = (j < J_DIM) ? labels[j] : 255;
    }

    float acc[4][4][4];
#pragma unroll
    for (int mb = 0; mb < 4; mb++)
#pragma unroll
        for (int nb = 0; nb < 4; nb++)
#pragma unroll
            for (int q = 0; q < 4; q++) acc[mb][nb][q] = 0.f;

    const uint4* gA = (const uint4*)(g_xb + (size_t)iBase * D_DIM);  // row stride = 64 uint4
    const uint4* gB = (const uint4*)(g_eb + (size_t)jBase * D_DIM);

    for (int kt = 0; kt < D_DIM / BK; kt++) {
        __syncthreads();
        // stage tiles: 512 uint4 per tile, 2 per thread
#pragma unroll
        for (int r = 0; r < 2; r++) {
            int idx = tid + r * 256;           // 0..511
            int row = idx >> 2, q = idx & 3;   // 128 rows x 4 uint4
            uint4 va = gA[row * 64 + kt * 4 + q];
            *(uint4*)&As[row * SSTRIDE + q * 4] = va;
            uint4 vb = gB[row * 64 + kt * 4 + q];
            *(uint4*)&Bs[row * SSTRIDE + q * 4] = vb;
        }
        __syncthreads();

#pragma unroll
        for (int ks = 0; ks < 2; ks++) {
            const int ko = ks * 8;  // u32 offset of this k16 step
            uint32_t a[4][4], b[4][2];
#pragma unroll
            for (int mb = 0; mb < 4; mb++) {
                int rb = wi * 64 + mb * 16 + gid;
                a[mb][0] = As[rb * SSTRIDE + ko + tig];
                a[mb][1] = As[(rb + 8) * SSTRIDE + ko + tig];
                a[mb][2] = As[rb * SSTRIDE + ko + tig + 4];
                a[mb][3] = As[(rb + 8) * SSTRIDE + ko + tig + 4];
            }
#pragma unroll
            for (int nb = 0; nb < 4; nb++) {
                int cb = wj * 32 + nb * 8 + gid;
                b[nb][0] = Bs[cb * SSTRIDE + ko + tig];
                b[nb][1] = Bs[cb * SSTRIDE + ko + tig + 4];
            }
#pragma unroll
            for (int mb = 0; mb < 4; mb++)
#pragma unroll
                for (int nb = 0; nb < 4; nb++)
                    mma_bf16(acc[mb][nb], a[mb], b[nb]);
        }
    }

    // ---------------- epilogue: dist -> exp -> per-class row sums ----------------
    float xs[4][2], es[4][2];
    int   lb[4][2];
#pragma unroll
    for (int mb = 0; mb < 4; mb++)
#pragma unroll
        for (int h = 0; h < 2; h++)
            xs[mb][h] = g_xsq[iBase + wi * 64 + mb * 16 + gid + h * 8];
#pragma unroll
    for (int nb = 0; nb < 4; nb++)
#pragma unroll
        for (int w = 0; w < 2; w++) {
            int cl = wj * 32 + nb * 8 + tig * 2 + w;
            es[nb][w] = g_esq[jBase + cl];
            lb[nb][w] = labs[cl];
        }

    // overwrite acc with attention = exp(-beta * dist)
#pragma unroll
    for (int mb = 0; mb < 4; mb++)
#pragma unroll
        for (int nb = 0; nb < 4; nb++)
#pragma unroll
            for (int h = 0; h < 2; h++)
#pragma unroll
                for (int w = 0; w < 2; w++) {
                    float d = xs[mb][h] + es[nb][w] - 2.f * acc[mb][nb][h * 2 + w];
                    acc[mb][nb][h * 2 + w] = __expf(-beta * d);
                }

#pragma unroll
    for (int c = 0; c < NCLS; c++) {
#pragma unroll
        for (int mb = 0; mb < 4; mb++)
#pragma unroll
            for (int h = 0; h < 2; h++) {
                float rs = 0.f;
#pragma unroll
                for (int nb = 0; nb < 4; nb++)
#pragma unroll
                    for (int w = 0; w < 2; w++)
                        rs += (lb[nb][w] == c) ? acc[mb][nb][h * 2 + w] : 0.f;
                rs += __shfl_xor_sync(0xffffffffu, rs, 1);
                rs += __shfl_xor_sync(0xffffffffu, rs, 2);
                if (tig == 0) {
                    int row = iBase + wi * 64 + mb * 16 + gid + h * 8;
                    atomicAdd(&g_logits[row * NCLS + c], rs);
                }
            }
    }
}

// ---------------- softmax over [I_DIM, 10] ----------------
__global__ void softmax_k(float* __restrict__ out, const float* __restrict__ gamma_p) {
    int row = blockIdx.x * blockDim.x + threadIdx.x;
    if (row >= I_DIM) return;
    float g = gamma_p[0];
    float v[NCLS];
    float m = -3.402823466e38f;
#pragma unroll
    for (int c = 0; c < NCLS; c++) {
        v[c] = g * g_logits[row * NCLS + c];
        m = fmaxf(m, v[c]);
    }
    float s = 0.f;
#pragma unroll
    for (int c = 0; c < NCLS; c++) { v[c] = __expf(v[c] - m); s += v[c]; }
    float inv = 1.f / s;
#pragma unroll
    for (int c = 0; c < NCLS; c++) out[row * NCLS + c] = v[c] * inv;
}

// ---------------- launch ----------------
extern "C" void kernel_launch(void* const* d_in, const int* in_sizes, int n_in,
                              void* d_out, int out_size) {
    const float* x      = (const float*)d_in[0];
    const float* ex     = (const float*)d_in[1];
    const int*   labels = (const int*)  d_in[2];
    const float* Sinv   = (const float*)d_in[3];
    const float* beta   = (const float*)d_in[4];
    const float* gamma  = (const float*)d_in[5];
    float* out = (float*)d_out;

    prep_x<<<I_DIM / 8, 256>>>(x, Sinv);          // 8 warps per 256-thread block
    prep_e<<<J_PAD / 8, 256>>>(ex, Sinv);
    zero_logits<<<(I_DIM * NCLS + 255) / 256, 256>>>();

    dim3 grid(I_DIM / BI, J_PAD / BJ);            // (8, 391); x-fastest => L2 reuse of E tiles
    gemm_fused<<<grid, 256>>>(labels, beta);

    softmax_k<<<(I_DIM + 255) / 256, 256>>>(out, gamma);
}

// round 3
// speedup vs baseline: 1.4352x; 1.4352x over previous
#include <cuda_runtime.h>
#include <cuda_bf16.h>
#include <cstdint>

#define I_DIM 1024
#define J_DIM 50000
#define J_PAD 50048            // 391 * 128
#define D_DIM 512
#define NCLS  10
#define BI 128
#define BJ 128
#define NCHUNK 8               // K chunks of 64 bf16 (128B per row)
#define STAGES 3

// ---- dynamic smem layout (bytes) ----
#define STAGE_BYTES 32768      // A 16KB + B 16KB
#define SM_LABS   (STAGES * STAGE_BYTES)        // 98304: 128 ints
#define SM_ESQ    (SM_LABS + 512)               // 128 floats
#define SM_LOGIT  (SM_ESQ + 512)                // 128*10 floats = 5120B
#define SM_TOTAL  (SM_LOGIT + 5120)             // 104448

// ---------------- device scratch ----------------
__device__ __align__(16) __nv_bfloat16 g_xb[I_DIM * D_DIM];   // x * Sigma_inv
__device__ __align__(16) __nv_bfloat16 g_eb[J_PAD * D_DIM];   // exemplars
__device__ float g_xsq[I_DIM];
__device__ float g_esq[J_PAD];
__device__ float g_logits[I_DIM * NCLS];

// ---------------- helpers ----------------
__device__ __forceinline__ uint32_t smem_u32(const void* p) {
    uint32_t a;
    asm("{ .reg .u64 t; cvta.to.shared.u64 t, %1; cvt.u32.u64 %0, t; }" : "=r"(a) : "l"(p));
    return a;
}
__device__ __forceinline__ void cp16(uint32_t dst, const void* src) {
    asm volatile("cp.async.cg.shared.global [%0], [%1], 16;" :: "r"(dst), "l"(src));
}
__device__ __forceinline__ void cp_commit() {
    asm volatile("cp.async.commit_group;" ::: "memory");
}
template <int N>
__device__ __forceinline__ void cp_wait() {
    asm volatile("cp.async.wait_group %0;" :: "n"(N) : "memory");
}
__device__ __forceinline__ void ldsm_x4(uint32_t r[4], uint32_t addr) {
    asm volatile("ldmatrix.sync.aligned.m8n8.x4.shared.b16 {%0,%1,%2,%3}, [%4];"
                 : "=r"(r[0]), "=r"(r[1]), "=r"(r[2]), "=r"(r[3]) : "r"(addr));
}
__device__ __forceinline__ void mma_bf16(float c[4], const uint32_t a[4], uint32_t b0, uint32_t b1) {
    asm volatile(
        "mma.sync.aligned.m16n8k16.row.col.f32.bf16.bf16.f32 "
        "{%0,%1,%2,%3}, {%4,%5,%6,%7}, {%8,%9}, {%0,%1,%2,%3};\n"
        : "+f"(c[0]), "+f"(c[1]), "+f"(c[2]), "+f"(c[3])
        : "r"(a[0]), "r"(a[1]), "r"(a[2]), "r"(a[3]), "r"(b0), "r"(b1));
}
__device__ __forceinline__ uint32_t pack_bf16(float lo, float hi) {
    uint32_t r;
    asm("cvt.rn.satfinite.bf16x2.f32 %0, %1, %2;" : "=r"(r) : "f"(hi), "f"(lo));
    return r;
}

// ---------------- prep: convert + row norms (vectorized) ----------------
__global__ void prep_x(const float4* __restrict__ x4, const float4* __restrict__ S4) {
    int row = blockIdx.x * 8 + (threadIdx.x >> 5);
    int lane = threadIdx.x & 31;
    float sq = 0.f;
    uint2* dst = ((uint2*)g_xb) + (size_t)row * 128;
#pragma unroll
    for (int i = 0; i < 4; i++) {
        int idx = i * 32 + lane;
        float4 v = x4[(size_t)row * 128 + idx];
        float4 s = S4[idx];
        float a0 = v.x * s.x, a1 = v.y * s.y, a2 = v.z * s.z, a3 = v.w * s.w;
        sq += v.x * a0 + v.y * a1 + v.z * a2 + v.w * a3;
        uint2 o; o.x = pack_bf16(a0, a1); o.y = pack_bf16(a2, a3);
        dst[idx] = o;
    }
#pragma unroll
    for (int o = 16; o; o >>= 1) sq += __shfl_xor_sync(0xffffffffu, sq, o);
    if (lane == 0) g_xsq[row] = sq;
}

__global__ void prep_e(const float4* __restrict__ e4, const float4* __restrict__ S4) {
    int row = blockIdx.x * 8 + (threadIdx.x >> 5);
    int lane = threadIdx.x & 31;
    uint2* dst = ((uint2*)g_eb) + (size_t)row * 128;
    if (row >= J_DIM) {
        uint2 z = {0u, 0u};
#pragma unroll
        for (int i = 0; i < 4; i++) dst[i * 32 + lane] = z;
        if (lane == 0) g_esq[row] = 0.f;
        return;
    }
    float sq = 0.f;
#pragma unroll
    for (int i = 0; i < 4; i++) {
        int idx = i * 32 + lane;
        float4 v = e4[(size_t)row * 128 + idx];
        float4 s = S4[idx];
        sq += v.x * v.x * s.x + v.y * v.y * s.y + v.z * v.z * s.z + v.w * v.w * s.w;
        uint2 o; o.x = pack_bf16(v.x, v.y); o.y = pack_bf16(v.z, v.w);
        dst[idx] = o;
    }
#pragma unroll
    for (int o = 16; o; o >>= 1) sq += __shfl_xor_sync(0xffffffffu, sq, o);
    if (lane == 0) g_esq[row] = sq;
}

__global__ void zero_logits() {
    int t = blockIdx.x * blockDim.x + threadIdx.x;
    if (t < I_DIM * NCLS) g_logits[t] = 0.f;
}

// ---------------- fused GEMM (ldmatrix + HMMA) + exp + segment-sum ----------------
__global__ __launch_bounds__(256, 2)
void gemm_fused(const int* __restrict__ labels, const float* __restrict__ beta_p) {
    extern __shared__ char smem[];
    const uint32_t sbase = smem_u32(smem);
    const int tid  = threadIdx.x;
    const int warp = tid >> 5;
    const int lane = tid & 31;
    const int gid  = lane >> 2;    // 0..7
    const int tig  = lane & 3;     // 0..3
    const int iBase = blockIdx.x * BI;
    const int jBase = blockIdx.y * BJ;
    const int wi = warp & 1;       // i-half (64 rows)
    const int wj = warp >> 1;      // j-quarter (32 cols)

    int*   labs_s  = (int*)(smem + SM_LABS);
    float* esq_s   = (float*)(smem + SM_ESQ);
    float* logit_s = (float*)(smem + SM_LOGIT);

    if (tid < BJ) {
        int j = jBase + tid;
        labs_s[tid] = (j < J_DIM) ? labels[j] : 255;
        esq_s[tid]  = g_esq[jBase + tid];
    }
#pragma unroll
    for (int i = tid; i < BI * NCLS; i += 256) logit_s[i] = 0.f;

    // ldmatrix per-lane address components (row&7 == lr for all our tiles)
    const int lr = lane & 7;
    const int aRowOff = lr + ((lane >> 3) & 1) * 8;
    const int aColSel = (lane >> 4) << 4;          // 0 or 16
    const int bRowOff = lr + (lane >> 4) * 8;
    const int bColSel = ((lane >> 3) & 1) << 4;    // 0 or 16
    const int swx = lr << 4;                       // swizzle xor term

    float acc[4][4][4];
#pragma unroll
    for (int mb = 0; mb < 4; mb++)
#pragma unroll
        for (int nb = 0; nb < 4; nb++)
#pragma unroll
            for (int q = 0; q < 4; q++) acc[mb][nb][q] = 0.f;

    const char* gA = (const char*)g_xb + (size_t)iBase * 1024;   // 1024B per row
    const char* gB = (const char*)g_eb + (size_t)jBase * 1024;

    // staging lambda-ish via macro: 4 iters A + 4 iters B, 16B each
#define STAGE_LOADS(chunk, buf)                                              \
    {                                                                        \
        const uint32_t dA = sbase + (buf) * STAGE_BYTES;                     \
        const uint32_t dB = dA + 16384;                                      \
        _Pragma("unroll")                                                    \
        for (int it = 0; it < 4; it++) {                                     \
            int idx = tid + it * 256;                                        \
            int r = idx >> 3, q = idx & 7;                                   \
            int off = r * 128 + ((q * 16) ^ ((r & 7) << 4));                 \
            cp16(dA + off, gA + (size_t)r * 1024 + (chunk) * 128 + q * 16);  \
            cp16(dB + off, gB + (size_t)r * 1024 + (chunk) * 128 + q * 16);  \
        }                                                                    \
    }

#pragma unroll
    for (int s = 0; s < STAGES; s++) { STAGE_LOADS(s, s); cp_commit(); }

    for (int kt = 0; kt < NCHUNK; kt++) {
        const int buf = kt % STAGES;
        cp_wait<STAGES - 1>();
        __syncthreads();

        const uint32_t aBase = sbase + buf * STAGE_BYTES;
        const uint32_t bBase = aBase + 16384;
#pragma unroll
        for (int ks = 0; ks < 4; ks++) {
            const int ko = ks * 32;
            uint32_t a[4][4], b[2][4];
#pragma unroll
            for (int mb = 0; mb < 4; mb++) {
                int row = wi * 64 + mb * 16 + aRowOff;
                ldsm_x4(a[mb], aBase + row * 128 + ((ko + aColSel) ^ swx));
            }
#pragma unroll
            for (int p = 0; p < 2; p++) {
                int row = wj * 32 + p * 16 + bRowOff;
                ldsm_x4(b[p], bBase + row * 128 + ((ko + bColSel) ^ swx));
            }
#pragma unroll
            for (int mb = 0; mb < 4; mb++)
#pragma unroll
                for (int nb = 0; nb < 4; nb++)
                    mma_bf16(acc[mb][nb], a[mb], b[nb >> 1][(nb & 1) * 2], b[nb >> 1][(nb & 1) * 2 + 1]);
        }
        __syncthreads();
        int nk = kt + STAGES;
        if (nk < NCHUNK) STAGE_LOADS(nk, buf);
        cp_commit();   // always commit (possibly empty) to keep wait_group math exact
    }

    // ---------------- epilogue: dist -> exp -> per-class row sums ----------------
    const float beta = beta_p[0];
    float xs[4][2], es[4][2];
    int   lb[4][2];
#pragma unroll
    for (int mb = 0; mb < 4; mb++)
#pragma unroll
        for (int h = 0; h < 2; h++)
            xs[mb][h] = g_xsq[iBase + wi * 64 + mb * 16 + gid + h * 8];
#pragma unroll
    for (int nb = 0; nb < 4; nb++)
#pragma unroll
        for (int w = 0; w < 2; w++) {
            int cl = wj * 32 + nb * 8 + tig * 2 + w;
            es[nb][w] = esq_s[cl];
            lb[nb][w] = labs_s[cl];
        }

#pragma unroll
    for (int mb = 0; mb < 4; mb++)
#pragma unroll
        for (int nb = 0; nb < 4; nb++)
#pragma unroll
            for (int h = 0; h < 2; h++)
#pragma unroll
                for (int w = 0; w < 2; w++) {
                    float d = xs[mb][h] + es[nb][w] - 2.f * acc[mb][nb][h * 2 + w];
                    acc[mb][nb][h * 2 + w] = __expf(-beta * d);
                }

#pragma unroll
    for (int c = 0; c < NCLS; c++) {
#pragma unroll
        for (int mb = 0; mb < 4; mb++)
#pragma unroll
            for (int h = 0; h < 2; h++) {
                float rs = 0.f;
#pragma unroll
                for (int nb = 0; nb < 4; nb++)
#pragma unroll
                    for (int w = 0; w < 2; w++)
                        rs += (lb[nb][w] == c) ? acc[mb][nb][h * 2 + w] : 0.f;
                rs += __shfl_xor_sync(0xffffffffu, rs, 1);
                rs += __shfl_xor_sync(0xffffffffu, rs, 2);
                if (tig == 0) {
                    int rloc = wi * 64 + mb * 16 + gid + h * 8;
                    atomicAdd(&logit_s[rloc * NCLS + c], rs);   // <=4-way (j-warps) smem contention
                }
            }
    }
    __syncthreads();

    // one global atomic per (row, class) per CTA
    for (int idx = tid; idx < BI * NCLS; idx += 256) {
        float v = logit_s[idx];
        atomicAdd(&g_logits[(iBase + idx / NCLS) * NCLS + (idx % NCLS)], v);
    }
#undef STAGE_LOADS
}

// ---------------- softmax over [I_DIM, 10] ----------------
__global__ void softmax_k(float* __restrict__ out, const float* __restrict__ gamma_p) {
    int row = blockIdx.x * blockDim.x + threadIdx.x;
    if (row >= I_DIM) return;
    float g = gamma_p[0];
    float v[NCLS];
    float m = -3.402823466e38f;
#pragma unroll
    for (int c = 0; c < NCLS; c++) {
        v[c] = g * g_logits[row * NCLS + c];
        m = fmaxf(m, v[c]);
    }
    float s = 0.f;
#pragma unroll
    for (int c = 0; c < NCLS; c++) { v[c] = __expf(v[c] - m); s += v[c]; }
    float inv = 1.f / s;
#pragma unroll
    for (int c = 0; c < NCLS; c++) out[row * NCLS + c] = v[c] * inv;
}

// ---------------- launch ----------------
extern "C" void kernel_launch(void* const* d_in, const int* in_sizes, int n_in,
                              void* d_out, int out_size) {
    const float* x      = (const float*)d_in[0];
    const float* ex     = (const float*)d_in[1];
    const int*   labels = (const int*)  d_in[2];
    const float* Sinv   = (const float*)d_in[3];
    const float* beta   = (const float*)d_in[4];
    const float* gamma  = (const float*)d_in[5];
    float* out = (float*)d_out;

    cudaFuncSetAttribute(gemm_fused, cudaFuncAttributeMaxDynamicSharedMemorySize, SM_TOTAL);

    prep_x<<<I_DIM / 8, 256>>>((const float4*)x, (const float4*)Sinv);
    prep_e<<<J_PAD / 8, 256>>>((const float4*)ex, (const float4*)Sinv);
    zero_logits<<<(I_DIM * NCLS + 255) / 256, 256>>>();

    dim3 grid(I_DIM / BI, J_PAD / BJ);   // (8, 391); x-fastest => 8 i-CTAs share each E tile in L2
    gemm_fused<<<grid, 256, SM_TOTAL>>>(labels, beta);

    softmax_k<<<(I_DIM + 255) / 256, 256>>>(out, gamma);
}